// round 13
// baseline (speedup 1.0000x reference)
#include <cuda_runtime.h>
#include <cuda_bf16.h>
#include <cstdint>

// Problem constants
#define BATCH 64
#define CHN   64
#define LSEQ  512
#define INTER 128
#define DCP   256
#define DDE   1024
#define KSEL  16
#define SCALE 0.05f

// Scratch (device globals; no runtime allocation)
__device__ __align__(16) __nv_bfloat16 g_mapraw[(size_t)CHN * LSEQ * INTER];
__device__ __align__(16) __nv_bfloat16 g_wcp1[INTER * DCP];
__device__ __align__(16) __nv_bfloat16 g_wcp2[DCP * DCP];
__device__ __align__(16) __nv_bfloat16 g_wde1[LSEQ * DDE];
__device__ __align__(16) __nv_bfloat16 g_wde2[DDE * LSEQ];
__device__ __align__(16) __nv_bfloat16 g_h1b[(size_t)CHN * LSEQ * DCP];
__device__ __align__(16) __nv_bfloat16 g_mapTb[(size_t)CHN * DCP * LSEQ];
__device__ __align__(16) __nv_bfloat16 g_h2b[(size_t)CHN * DCP * DDE];
__device__ __align__(16) __nv_bfloat16 g_mapst[(size_t)CHN * DCP * LSEQ];

__device__ __forceinline__ uint32_t packbf(float lo, float hi) {
    uint32_t r;
    asm("cvt.rn.bf16x2.f32 %0, %1, %2;" : "=r"(r) : "f"(hi), "f"(lo));
    return r;
}

// ---------------------------------------------------------------------------
// Single merged f32->bf16 convert over all 5 tensors.
// ---------------------------------------------------------------------------
#define N_MAPRAW (CHN * LSEQ * INTER)
#define N_WCP1   (INTER * DCP)
#define N_WCP2   (DCP * DCP)
#define N_WDE1   (LSEQ * DDE)
#define N_WDE2   (DDE * LSEQ)
#define N_CVT_TOT (N_MAPRAW + N_WCP1 + N_WCP2 + N_WDE1 + N_WDE2)

__global__ void cvt_all(const float* __restrict__ s0, __nv_bfloat16* __restrict__ d0,
                        const float* __restrict__ s1, __nv_bfloat16* __restrict__ d1,
                        const float* __restrict__ s2, __nv_bfloat16* __restrict__ d2,
                        const float* __restrict__ s3, __nv_bfloat16* __restrict__ d3,
                        const float* __restrict__ s4, __nv_bfloat16* __restrict__ d4)
{
    int i = (blockIdx.x * blockDim.x + threadIdx.x) * 4;
    const float* s;
    __nv_bfloat16* d;
    if (i < N_MAPRAW)                          { s = s0; d = d0; }
    else if ((i -= N_MAPRAW) < N_WCP1)         { s = s1; d = d1; }
    else if ((i -= N_WCP1) < N_WCP2)           { s = s2; d = d2; }
    else if ((i -= N_WCP2) < N_WDE1)           { s = s3; d = d3; }
    else          { i -= N_WDE1;                 s = s4; d = d4; }
    float4 v = *(const float4*)(s + i);
    uint2 o;
    o.x = packbf(v.x, v.y);
    o.y = packbf(v.z, v.w);
    *(uint2*)(d + i) = o;
}

// ---------------------------------------------------------------------------
// BF16 tensor-core GEMM, cp.async 3-stage pipeline + ldmatrix, BK=64.
// 256 threads, 8 warps 4(M)x2(N), warp tile 32x64 (R11 optimum).
// ISSUE(kt+2) deferred until after ks=0 fragment loads (critical-path reorder).
// K, N template parameters.
// ---------------------------------------------------------------------------
#define BM 128
#define BN 128
#define BK 64
#define STAGES 3
#define ASTAGE 16384
#define BSTAGE 16384
#define GSMEM (STAGES * (ASTAGE + BSTAGE))   // 98304
#define EPI_STRIDE 136

__device__ __forceinline__ void cpasync16(uint32_t saddr, const void* gaddr) {
    asm volatile("cp.async.cg.shared.global [%0], [%1], 16;" :: "r"(saddr), "l"(gaddr));
}
__device__ __forceinline__ void ldsm4(uint32_t& r0, uint32_t& r1, uint32_t& r2, uint32_t& r3, uint32_t a) {
    asm volatile("ldmatrix.sync.aligned.m8n8.x4.shared.b16 {%0,%1,%2,%3}, [%4];"
                 : "=r"(r0), "=r"(r1), "=r"(r2), "=r"(r3) : "r"(a));
}
__device__ __forceinline__ void ldsm4t(uint32_t& r0, uint32_t& r1, uint32_t& r2, uint32_t& r3, uint32_t a) {
    asm volatile("ldmatrix.sync.aligned.m8n8.x4.trans.shared.b16 {%0,%1,%2,%3}, [%4];"
                 : "=r"(r0), "=r"(r1), "=r"(r2), "=r"(r3) : "r"(a));
}

template<int K, int N, bool RELU, bool SWAP>
__global__ __launch_bounds__(256, 2) void gemm_bf(const __nv_bfloat16* __restrict__ A,
                                                  const __nv_bfloat16* __restrict__ B,
                                                  const float* __restrict__ bias,
                                                  __nv_bfloat16* __restrict__ Cout)
{
    extern __shared__ __align__(16) char smem[];
    const uint32_t sA = (uint32_t)__cvta_generic_to_shared(smem);
    const uint32_t sB = sA + STAGES * ASTAGE;

    const int t    = threadIdx.x;
    const int lane = t & 31;
    const int w    = t >> 5;
    const int wm   = (w & 3) * 32;
    const int wn   = (w >> 2) * 64;
    const int bm   = blockIdx.y * BM;
    const int bn   = blockIdx.x * BN;

    constexpr int ntiles = K / BK;

#define ISSUE(kt)                                                                     \
    do {                                                                              \
        if ((kt) < ntiles) {                                                          \
            const uint32_t ab = sA + (uint32_t)(((kt) % STAGES)) * ASTAGE;            \
            const uint32_t bb = sB + (uint32_t)(((kt) % STAGES)) * BSTAGE;            \
            _Pragma("unroll")                                                         \
            for (int q4 = 0; q4 < 4; q4++) {                                          \
                const int qa   = t + q4 * 256;                                        \
                const int arow = qa >> 3;                                             \
                const int acc_ = qa & 7;                                              \
                const uint32_t aoff = (uint32_t)((arow * 8 + (acc_ ^ (arow & 7))) * 16); \
                cpasync16(ab + aoff,                                                  \
                          A + (size_t)(bm + arow) * K + (kt) * BK + acc_ * 8);        \
                const int bk  = qa >> 4;                                              \
                const int bcc = qa & 15;                                              \
                const uint32_t boff = (uint32_t)((bk * 16 + ((bcc & 8) | ((bcc & 7) ^ (bk & 7)))) * 16); \
                cpasync16(bb + boff,                                                  \
                          B + (size_t)((kt) * BK + bk) * N + bn + bcc * 8);           \
            }                                                                         \
        }                                                                             \
        asm volatile("cp.async.commit_group;");                                       \
    } while (0)

    float acc[2][8][4];
    #pragma unroll
    for (int i = 0; i < 2; i++)
        #pragma unroll
        for (int j = 0; j < 8; j++)
            #pragma unroll
            for (int q = 0; q < 4; q++) acc[i][j][q] = 0.0f;

    ISSUE(0);
    ISSUE(1);
    asm volatile("cp.async.wait_group 1;");
    __syncthreads();

    #pragma unroll 3
    for (int kt = 0; kt < ntiles; kt++) {
        const uint32_t curA = sA + (uint32_t)(kt % STAGES) * ASTAGE;
        const uint32_t curB = sB + (uint32_t)(kt % STAGES) * BSTAGE;

        #pragma unroll
        for (int ks = 0; ks < 4; ks++) {
            uint32_t af[2][4];
            {
                const int cch = ks * 2 + (lane >> 4);
                #pragma unroll
                for (int mi = 0; mi < 2; mi++) {
                    const int m = wm + mi * 16 + (lane & 15);
                    const uint32_t a = curA + (uint32_t)((m * 8 + (cch ^ (m & 7))) * 16);
                    ldsm4(af[mi][0], af[mi][1], af[mi][2], af[mi][3], a);
                }
            }
            uint32_t bf[4][4];
            {
                const int k = ks * 16 + (lane & 7) + 8 * ((lane >> 3) & 1);
                const int nc0 = (wn >> 3) + (lane >> 4);
                #pragma unroll
                for (int j = 0; j < 4; j++) {
                    const int nc = nc0 + 2 * j;
                    const uint32_t swz = (uint32_t)((nc & 8) | ((nc & 7) ^ (k & 7)));
                    const uint32_t a = curB + (uint32_t)(k * 256) + swz * 16;
                    ldsm4t(bf[j][0], bf[j][1], bf[j][2], bf[j][3], a);
                }
            }
            // Defer the next-tile copy burst until after the first fragment loads:
            // the ks=0 ldsm->mma chain starts immediately post-barrier, and the
            // cp.async burst overlaps the ks=0 MMA block instead of preceding it.
            if (ks == 0) ISSUE(kt + 2);
            #pragma unroll
            for (int ni = 0; ni < 8; ni++) {
                const uint32_t b0 = bf[ni >> 1][(ni & 1) * 2 + 0];
                const uint32_t b1 = bf[ni >> 1][(ni & 1) * 2 + 1];
                #pragma unroll
                for (int mi = 0; mi < 2; mi++) {
                    asm volatile(
                        "mma.sync.aligned.m16n8k16.row.col.f32.bf16.bf16.f32 "
                        "{%0,%1,%2,%3}, {%4,%5,%6,%7}, {%8,%9}, {%0,%1,%2,%3};"
                        : "+f"(acc[mi][ni][0]), "+f"(acc[mi][ni][1]),
                          "+f"(acc[mi][ni][2]), "+f"(acc[mi][ni][3])
                        : "r"(af[mi][0]), "r"(af[mi][1]), "r"(af[mi][2]), "r"(af[mi][3]),
                          "r"(b0), "r"(b1));
                }
            }
        }

        asm volatile("cp.async.wait_group 1;");
        __syncthreads();
    }
#undef ISSUE

    if (SWAP) {
        __nv_bfloat16* epi = (__nv_bfloat16*)smem;
        __syncthreads();
        #pragma unroll
        for (int mi = 0; mi < 2; mi++) {
            const int r = wm + mi * 16 + (lane >> 2);
            #pragma unroll
            for (int ni = 0; ni < 8; ni++) {
                const int col = wn + ni * 8 + 2 * (lane & 3);
                const float bv0 = bias[bn + col];
                const float bv1 = bias[bn + col + 1];
                #pragma unroll
                for (int h = 0; h < 2; h++) {
                    const int m = r + h * 8;
                    float v0 = acc[mi][ni][h * 2 + 0] + bv0;
                    float v1 = acc[mi][ni][h * 2 + 1] + bv1;
                    if (RELU) { v0 = fmaxf(v0, 0.0f); v1 = fmaxf(v1, 0.0f); }
                    epi[(size_t)col * EPI_STRIDE + m]       = __float2bfloat16(v0);
                    epi[(size_t)(col + 1) * EPI_STRIDE + m] = __float2bfloat16(v1);
                }
            }
        }
        __syncthreads();
        const int c  = bm >> 9;
        const int l0 = bm & 511;
        #pragma unroll
        for (int i = t; i < 128 * 16; i += 256) {
            const int col = i >> 4, chunk = i & 15;
            uint4 v = *(uint4*)(epi + (size_t)col * EPI_STRIDE + chunk * 8);
            *(uint4*)(Cout + ((size_t)c * DCP + bn + col) * LSEQ + l0 + chunk * 8) = v;
        }
    } else {
        #pragma unroll
        for (int mi = 0; mi < 2; mi++) {
            const int r = bm + wm + mi * 16 + (lane >> 2);
            #pragma unroll
            for (int ni = 0; ni < 8; ni++) {
                const int col = bn + wn + ni * 8 + 2 * (lane & 3);
                const float bv0 = bias[col];
                const float bv1 = bias[col + 1];
                #pragma unroll
                for (int h = 0; h < 2; h++) {
                    const int m = r + h * 8;
                    float v0 = acc[mi][ni][h * 2 + 0] + bv0;
                    float v1 = acc[mi][ni][h * 2 + 1] + bv1;
                    if (RELU) { v0 = fmaxf(v0, 0.0f); v1 = fmaxf(v1, 0.0f); }
                    *(uint32_t*)(Cout + (size_t)m * N + col) = packbf(v0, v1);
                }
            }
        }
    }
}

// ---------------------------------------------------------------------------
// Fused tail: gather K rows (bf16), L1 scores, softmax, weighted sum, blend.
// ---------------------------------------------------------------------------
__global__ __launch_bounds__(256) void fuse_k(const float* __restrict__ x_loc,
                                              const __nv_bfloat16* __restrict__ map_st,
                                              const int*   __restrict__ indices,
                                              const float* __restrict__ lamda1,
                                              const float* __restrict__ lamda2,
                                              float* __restrict__ out)
{
    __shared__ float xs[LSEQ];
    __shared__ __nv_bfloat16 ms[KSEL][LSEQ];
    __shared__ float warpsum[KSEL][8];
    __shared__ float wgt[KSEL];

    const int bc = blockIdx.x;
    const int c  = bc & (CHN - 1);
    const int t  = threadIdx.x;

    const float* xrow = x_loc + (size_t)bc * LSEQ;
    for (int i = t; i < LSEQ; i += 256) xs[i] = xrow[i];

    #pragma unroll
    for (int q = 0; q < 4; q++) {
        const int idx = t + q * 256;
        const int k = idx >> 6, chunk = idx & 63;
        const int d = indices[bc * KSEL + k];
        const uint4* src = (const uint4*)(map_st + ((size_t)c * DCP + d) * LSEQ) + chunk;
        ((uint4*)&ms[k][0])[chunk] = src[0];
    }
    __syncthreads();

    float part[KSEL];
    #pragma unroll
    for (int k = 0; k < KSEL; k++) part[k] = 0.0f;
    for (int i = t; i < LSEQ; i += 256) {
        const float x = xs[i];
        #pragma unroll
        for (int k = 0; k < KSEL; k++) part[k] += fabsf(x - __bfloat162float(ms[k][i]));
    }

    const int lane = t & 31, w = t >> 5;
    #pragma unroll
    for (int k = 0; k < KSEL; k++) {
        float v = part[k];
        #pragma unroll
        for (int off = 16; off > 0; off >>= 1)
            v += __shfl_down_sync(0xffffffffu, v, off);
        if (lane == 0) warpsum[k][w] = v;
    }
    __syncthreads();

    if (t < KSEL) {
        float s = 0.0f;
        #pragma unroll
        for (int ww = 0; ww < 8; ww++) s += warpsum[t][ww];
        float score = -s * SCALE;
        float mx = score;
        #pragma unroll
        for (int off = 8; off > 0; off >>= 1)
            mx = fmaxf(mx, __shfl_xor_sync(0x0000ffffu, mx, off));
        float e  = expf(score - mx);
        float se = e;
        #pragma unroll
        for (int off = 8; off > 0; off >>= 1)
            se += __shfl_xor_sync(0x0000ffffu, se, off);
        wgt[t] = e / se;
    }
    __syncthreads();

    const float s1 = 1.0f / (1.0f + expf(-lamda1[c]));
    float* orow = out + (size_t)bc * LSEQ;
    for (int i = t; i < LSEQ; i += 256) {
        float g = 0.0f;
        #pragma unroll
        for (int k = 0; k < KSEL; k++) g = fmaf(wgt[k], __bfloat162float(ms[k][i]), g);
        const float s2  = 1.0f / (1.0f + expf(-lamda2[i]));
        const float lam = s1 * s2;
        orow[i] = g * lam + xs[i] * (1.0f - lam);
    }
}

// ---------------------------------------------------------------------------
static void* symaddr(const void* sym)
{
    void* p = nullptr;
    cudaGetSymbolAddress(&p, sym);
    return p;
}

extern "C" void kernel_launch(void* const* d_in, const int* in_sizes, int n_in,
                              void* d_out, int out_size)
{
    const float* x_loc   = (const float*)d_in[0];
    const float* map_raw = (const float*)d_in[1];
    const float* cp_w1   = (const float*)d_in[2];
    const float* cp_b1   = (const float*)d_in[3];
    const float* cp_w2   = (const float*)d_in[4];
    const float* cp_b2   = (const float*)d_in[5];
    const float* de_w1   = (const float*)d_in[6];
    const float* de_b1   = (const float*)d_in[7];
    const float* de_w2   = (const float*)d_in[8];
    const float* de_b2   = (const float*)d_in[9];
    const float* lamda1  = (const float*)d_in[10];
    const float* lamda2  = (const float*)d_in[11];
    const int*   indices = (const int*)d_in[12];
    float* out = (float*)d_out;

    __nv_bfloat16* mapraw = (__nv_bfloat16*)symaddr(g_mapraw);
    __nv_bfloat16* wcp1   = (__nv_bfloat16*)symaddr(g_wcp1);
    __nv_bfloat16* wcp2   = (__nv_bfloat16*)symaddr(g_wcp2);
    __nv_bfloat16* wde1   = (__nv_bfloat16*)symaddr(g_wde1);
    __nv_bfloat16* wde2   = (__nv_bfloat16*)symaddr(g_wde2);
    __nv_bfloat16* h1b    = (__nv_bfloat16*)symaddr(g_h1b);
    __nv_bfloat16* mapTb  = (__nv_bfloat16*)symaddr(g_mapTb);
    __nv_bfloat16* h2b    = (__nv_bfloat16*)symaddr(g_h2b);
    __nv_bfloat16* mapst  = (__nv_bfloat16*)symaddr(g_mapst);

    const int M1 = CHN * LSEQ;   // 32768
    const int M3 = CHN * DCP;    // 16384

    cudaFuncSetAttribute(gemm_bf<INTER, DCP,  true,  false>, cudaFuncAttributeMaxDynamicSharedMemorySize, GSMEM);
    cudaFuncSetAttribute(gemm_bf<DCP,   DCP,  false, true >, cudaFuncAttributeMaxDynamicSharedMemorySize, GSMEM);
    cudaFuncSetAttribute(gemm_bf<LSEQ,  DDE,  true,  false>, cudaFuncAttributeMaxDynamicSharedMemorySize, GSMEM);
    cudaFuncSetAttribute(gemm_bf<DDE,   LSEQ, false, false>, cudaFuncAttributeMaxDynamicSharedMemorySize, GSMEM);

    cvt_all<<<N_CVT_TOT / 4 / 256, 256>>>(map_raw, mapraw, cp_w1, wcp1, cp_w2, wcp2,
                                          de_w1, wde1, de_w2, wde2);

    // GEMM1: (32768,128)@(128,256) + b, relu -> h1 (bf16)
    gemm_bf<INTER, DCP,  true,  false><<<dim3(DCP / BN, M1 / BM), 256, GSMEM>>>(mapraw, wcp1, cp_b1, h1b);
    // GEMM2: (32768,256)@(256,256) + b -> mapT (bf16, transposed store via smem)
    gemm_bf<DCP,   DCP,  false, true ><<<dim3(DCP / BN, M1 / BM), 256, GSMEM>>>(h1b, wcp2, cp_b2, mapTb);
    // GEMM3: (16384,512)@(512,1024) + b, relu -> h2 (bf16)
    gemm_bf<LSEQ,  DDE,  true,  false><<<dim3(DDE / BN, M3 / BM), 256, GSMEM>>>(mapTb, wde1, de_b1, h2b);
    // GEMM4: (16384,1024)@(1024,512) + b -> mapst (bf16)
    gemm_bf<DDE,   LSEQ, false, false><<<dim3(LSEQ / BN, M3 / BM), 256, GSMEM>>>(h2b, wde2, de_b2, mapst);
    // Fused gather/score/softmax/blend (bf16 map_st)
    fuse_k<<<BATCH * CHN, 256>>>(x_loc, mapst, indices, lamda1, lamda2, out);
}

// round 14
// speedup vs baseline: 1.0471x; 1.0471x over previous
#include <cuda_runtime.h>
#include <cuda_bf16.h>
#include <cstdint>

// Problem constants
#define BATCH 64
#define CHN   64
#define LSEQ  512
#define INTER 128
#define DCP   256
#define DDE   1024
#define KSEL  16
#define SCALE 0.05f

// Scratch (device globals; no runtime allocation)
__device__ __align__(16) __nv_bfloat16 g_mapraw[(size_t)CHN * LSEQ * INTER];
__device__ __align__(16) __nv_bfloat16 g_wcp1[INTER * DCP];
__device__ __align__(16) __nv_bfloat16 g_wcp2[DCP * DCP];
__device__ __align__(16) __nv_bfloat16 g_wde1[LSEQ * DDE];
__device__ __align__(16) __nv_bfloat16 g_wde2[DDE * LSEQ];
__device__ __align__(16) __nv_bfloat16 g_h1b[(size_t)CHN * LSEQ * DCP];
__device__ __align__(16) __nv_bfloat16 g_mapTb[(size_t)CHN * DCP * LSEQ];
__device__ __align__(16) __nv_bfloat16 g_h2b[(size_t)CHN * DCP * DDE];
__device__ __align__(16) __nv_bfloat16 g_mapst[(size_t)CHN * DCP * LSEQ];

__device__ __forceinline__ uint32_t packbf(float lo, float hi) {
    uint32_t r;
    asm("cvt.rn.bf16x2.f32 %0, %1, %2;" : "=r"(r) : "f"(hi), "f"(lo));
    return r;
}

// ---------------------------------------------------------------------------
// Single merged f32->bf16 convert over all 5 tensors.
// ---------------------------------------------------------------------------
#define N_MAPRAW (CHN * LSEQ * INTER)
#define N_WCP1   (INTER * DCP)
#define N_WCP2   (DCP * DCP)
#define N_WDE1   (LSEQ * DDE)
#define N_WDE2   (DDE * LSEQ)
#define N_CVT_TOT (N_MAPRAW + N_WCP1 + N_WCP2 + N_WDE1 + N_WDE2)

__global__ void cvt_all(const float* __restrict__ s0, __nv_bfloat16* __restrict__ d0,
                        const float* __restrict__ s1, __nv_bfloat16* __restrict__ d1,
                        const float* __restrict__ s2, __nv_bfloat16* __restrict__ d2,
                        const float* __restrict__ s3, __nv_bfloat16* __restrict__ d3,
                        const float* __restrict__ s4, __nv_bfloat16* __restrict__ d4)
{
    int i = (blockIdx.x * blockDim.x + threadIdx.x) * 4;
    const float* s;
    __nv_bfloat16* d;
    if (i < N_MAPRAW)                          { s = s0; d = d0; }
    else if ((i -= N_MAPRAW) < N_WCP1)         { s = s1; d = d1; }
    else if ((i -= N_WCP1) < N_WCP2)           { s = s2; d = d2; }
    else if ((i -= N_WCP2) < N_WDE1)           { s = s3; d = d3; }
    else          { i -= N_WDE1;                 s = s4; d = d4; }
    float4 v = *(const float4*)(s + i);
    uint2 o;
    o.x = packbf(v.x, v.y);
    o.y = packbf(v.z, v.w);
    *(uint2*)(d + i) = o;
}

// ---------------------------------------------------------------------------
// BF16 tensor-core GEMM, cp.async 3-stage pipeline + ldmatrix, BK=64.
// 256 threads, 8 warps 4(M)x2(N), warp tile 32x64 (R11 optimum, exact).
// K, N template parameters.
// ---------------------------------------------------------------------------
#define BM 128
#define BN 128
#define BK 64
#define STAGES 3
#define ASTAGE 16384
#define BSTAGE 16384
#define GSMEM (STAGES * (ASTAGE + BSTAGE))   // 98304
#define EPI_STRIDE 136

__device__ __forceinline__ void cpasync16(uint32_t saddr, const void* gaddr) {
    asm volatile("cp.async.cg.shared.global [%0], [%1], 16;" :: "r"(saddr), "l"(gaddr));
}
__device__ __forceinline__ void ldsm4(uint32_t& r0, uint32_t& r1, uint32_t& r2, uint32_t& r3, uint32_t a) {
    asm volatile("ldmatrix.sync.aligned.m8n8.x4.shared.b16 {%0,%1,%2,%3}, [%4];"
                 : "=r"(r0), "=r"(r1), "=r"(r2), "=r"(r3) : "r"(a));
}
__device__ __forceinline__ void ldsm4t(uint32_t& r0, uint32_t& r1, uint32_t& r2, uint32_t& r3, uint32_t a) {
    asm volatile("ldmatrix.sync.aligned.m8n8.x4.trans.shared.b16 {%0,%1,%2,%3}, [%4];"
                 : "=r"(r0), "=r"(r1), "=r"(r2), "=r"(r3) : "r"(a));
}

template<int K, int N, bool RELU, bool SWAP>
__global__ __launch_bounds__(256, 2) void gemm_bf(const __nv_bfloat16* __restrict__ A,
                                                  const __nv_bfloat16* __restrict__ B,
                                                  const float* __restrict__ bias,
                                                  __nv_bfloat16* __restrict__ Cout)
{
    extern __shared__ __align__(16) char smem[];
    const uint32_t sA = (uint32_t)__cvta_generic_to_shared(smem);
    const uint32_t sB = sA + STAGES * ASTAGE;

    const int t    = threadIdx.x;
    const int lane = t & 31;
    const int w    = t >> 5;
    const int wm   = (w & 3) * 32;
    const int wn   = (w >> 2) * 64;
    const int bm   = blockIdx.y * BM;
    const int bn   = blockIdx.x * BN;

    constexpr int ntiles = K / BK;

#define ISSUE(kt)                                                                     \
    do {                                                                              \
        if ((kt) < ntiles) {                                                          \
            const uint32_t ab = sA + (uint32_t)(((kt) % STAGES)) * ASTAGE;            \
            const uint32_t bb = sB + (uint32_t)(((kt) % STAGES)) * BSTAGE;            \
            _Pragma("unroll")                                                         \
            for (int q4 = 0; q4 < 4; q4++) {                                          \
                const int qa   = t + q4 * 256;                                        \
                const int arow = qa >> 3;                                             \
                const int acc_ = qa & 7;                                              \
                const uint32_t aoff = (uint32_t)((arow * 8 + (acc_ ^ (arow & 7))) * 16); \
                cpasync16(ab + aoff,                                                  \
                          A + (size_t)(bm + arow) * K + (kt) * BK + acc_ * 8);        \
                const int bk  = qa >> 4;                                              \
                const int bcc = qa & 15;                                              \
                const uint32_t boff = (uint32_t)((bk * 16 + ((bcc & 8) | ((bcc & 7) ^ (bk & 7)))) * 16); \
                cpasync16(bb + boff,                                                  \
                          B + (size_t)((kt) * BK + bk) * N + bn + bcc * 8);           \
            }                                                                         \
        }                                                                             \
        asm volatile("cp.async.commit_group;");                                       \
    } while (0)

    float acc[2][8][4];
    #pragma unroll
    for (int i = 0; i < 2; i++)
        #pragma unroll
        for (int j = 0; j < 8; j++)
            #pragma unroll
            for (int q = 0; q < 4; q++) acc[i][j][q] = 0.0f;

    ISSUE(0);
    ISSUE(1);
    asm volatile("cp.async.wait_group 1;");
    __syncthreads();

    #pragma unroll 3
    for (int kt = 0; kt < ntiles; kt++) {
        ISSUE(kt + 2);

        const uint32_t curA = sA + (uint32_t)(kt % STAGES) * ASTAGE;
        const uint32_t curB = sB + (uint32_t)(kt % STAGES) * BSTAGE;

        #pragma unroll
        for (int ks = 0; ks < 4; ks++) {
            uint32_t af[2][4];
            {
                const int cch = ks * 2 + (lane >> 4);
                #pragma unroll
                for (int mi = 0; mi < 2; mi++) {
                    const int m = wm + mi * 16 + (lane & 15);
                    const uint32_t a = curA + (uint32_t)((m * 8 + (cch ^ (m & 7))) * 16);
                    ldsm4(af[mi][0], af[mi][1], af[mi][2], af[mi][3], a);
                }
            }
            uint32_t bf[4][4];
            {
                const int k = ks * 16 + (lane & 7) + 8 * ((lane >> 3) & 1);
                const int nc0 = (wn >> 3) + (lane >> 4);
                #pragma unroll
                for (int j = 0; j < 4; j++) {
                    const int nc = nc0 + 2 * j;
                    const uint32_t swz = (uint32_t)((nc & 8) | ((nc & 7) ^ (k & 7)));
                    const uint32_t a = curB + (uint32_t)(k * 256) + swz * 16;
                    ldsm4t(bf[j][0], bf[j][1], bf[j][2], bf[j][3], a);
                }
            }
            #pragma unroll
            for (int ni = 0; ni < 8; ni++) {
                const uint32_t b0 = bf[ni >> 1][(ni & 1) * 2 + 0];
                const uint32_t b1 = bf[ni >> 1][(ni & 1) * 2 + 1];
                #pragma unroll
                for (int mi = 0; mi < 2; mi++) {
                    asm volatile(
                        "mma.sync.aligned.m16n8k16.row.col.f32.bf16.bf16.f32 "
                        "{%0,%1,%2,%3}, {%4,%5,%6,%7}, {%8,%9}, {%0,%1,%2,%3};"
                        : "+f"(acc[mi][ni][0]), "+f"(acc[mi][ni][1]),
                          "+f"(acc[mi][ni][2]), "+f"(acc[mi][ni][3])
                        : "r"(af[mi][0]), "r"(af[mi][1]), "r"(af[mi][2]), "r"(af[mi][3]),
                          "r"(b0), "r"(b1));
                }
            }
        }

        asm volatile("cp.async.wait_group 1;");
        __syncthreads();
    }
#undef ISSUE

    if (SWAP) {
        __nv_bfloat16* epi = (__nv_bfloat16*)smem;
        __syncthreads();
        #pragma unroll
        for (int mi = 0; mi < 2; mi++) {
            const int r = wm + mi * 16 + (lane >> 2);
            #pragma unroll
            for (int ni = 0; ni < 8; ni++) {
                const int col = wn + ni * 8 + 2 * (lane & 3);
                const float bv0 = bias[bn + col];
                const float bv1 = bias[bn + col + 1];
                #pragma unroll
                for (int h = 0; h < 2; h++) {
                    const int m = r + h * 8;
                    float v0 = acc[mi][ni][h * 2 + 0] + bv0;
                    float v1 = acc[mi][ni][h * 2 + 1] + bv1;
                    if (RELU) { v0 = fmaxf(v0, 0.0f); v1 = fmaxf(v1, 0.0f); }
                    epi[(size_t)col * EPI_STRIDE + m]       = __float2bfloat16(v0);
                    epi[(size_t)(col + 1) * EPI_STRIDE + m] = __float2bfloat16(v1);
                }
            }
        }
        __syncthreads();
        const int c  = bm >> 9;
        const int l0 = bm & 511;
        #pragma unroll
        for (int i = t; i < 128 * 16; i += 256) {
            const int col = i >> 4, chunk = i & 15;
            uint4 v = *(uint4*)(epi + (size_t)col * EPI_STRIDE + chunk * 8);
            *(uint4*)(Cout + ((size_t)c * DCP + bn + col) * LSEQ + l0 + chunk * 8) = v;
        }
    } else {
        #pragma unroll
        for (int mi = 0; mi < 2; mi++) {
            const int r = bm + wm + mi * 16 + (lane >> 2);
            #pragma unroll
            for (int ni = 0; ni < 8; ni++) {
                const int col = bn + wn + ni * 8 + 2 * (lane & 3);
                const float bv0 = bias[col];
                const float bv1 = bias[col + 1];
                #pragma unroll
                for (int h = 0; h < 2; h++) {
                    const int m = r + h * 8;
                    float v0 = acc[mi][ni][h * 2 + 0] + bv0;
                    float v1 = acc[mi][ni][h * 2 + 1] + bv1;
                    if (RELU) { v0 = fmaxf(v0, 0.0f); v1 = fmaxf(v1, 0.0f); }
                    *(uint32_t*)(Cout + (size_t)m * N + col) = packbf(v0, v1);
                }
            }
        }
    }
}

// ---------------------------------------------------------------------------
// Fused tail: cp.async gather of K bf16 rows + x, L1 scores, softmax, blend.
// ---------------------------------------------------------------------------
__global__ __launch_bounds__(256) void fuse_k(const float* __restrict__ x_loc,
                                              const __nv_bfloat16* __restrict__ map_st,
                                              const int*   __restrict__ indices,
                                              const float* __restrict__ lamda1,
                                              const float* __restrict__ lamda2,
                                              float* __restrict__ out)
{
    __shared__ __align__(16) float xs[LSEQ];
    __shared__ __align__(16) __nv_bfloat16 ms[KSEL][LSEQ];
    __shared__ float warpsum[KSEL][8];
    __shared__ float wgt[KSEL];

    const int bc = blockIdx.x;
    const int c  = bc & (CHN - 1);
    const int t  = threadIdx.x;

    // cp.async staging: x row (2KB = 128 chunks) + 16 map rows (64 chunks each)
    const uint32_t sxs = (uint32_t)__cvta_generic_to_shared(xs);
    const uint32_t sms = (uint32_t)__cvta_generic_to_shared(ms);

    {
        const float* xrow = x_loc + (size_t)bc * LSEQ;
        if (t < 128) cpasync16(sxs + t * 16, xrow + t * 4);
        #pragma unroll
        for (int q = 0; q < 4; q++) {
            const int idx = t + q * 256;           // 0..1023
            const int k = idx >> 6, chunk = idx & 63;
            const int d = indices[bc * KSEL + k];
            cpasync16(sms + (uint32_t)(k * LSEQ * 2 + chunk * 16),
                      map_st + ((size_t)c * DCP + d) * LSEQ + chunk * 8);
        }
        asm volatile("cp.async.commit_group;");
        asm volatile("cp.async.wait_group 0;");
    }
    __syncthreads();

    float part[KSEL];
    #pragma unroll
    for (int k = 0; k < KSEL; k++) part[k] = 0.0f;
    for (int i = t; i < LSEQ; i += 256) {
        const float x = xs[i];
        #pragma unroll
        for (int k = 0; k < KSEL; k++) part[k] += fabsf(x - __bfloat162float(ms[k][i]));
    }

    const int lane = t & 31, w = t >> 5;
    #pragma unroll
    for (int k = 0; k < KSEL; k++) {
        float v = part[k];
        #pragma unroll
        for (int off = 16; off > 0; off >>= 1)
            v += __shfl_down_sync(0xffffffffu, v, off);
        if (lane == 0) warpsum[k][w] = v;
    }
    __syncthreads();

    if (t < KSEL) {
        float s = 0.0f;
        #pragma unroll
        for (int ww = 0; ww < 8; ww++) s += warpsum[t][ww];
        float score = -s * SCALE;
        float mx = score;
        #pragma unroll
        for (int off = 8; off > 0; off >>= 1)
            mx = fmaxf(mx, __shfl_xor_sync(0x0000ffffu, mx, off));
        float e  = expf(score - mx);
        float se = e;
        #pragma unroll
        for (int off = 8; off > 0; off >>= 1)
            se += __shfl_xor_sync(0x0000ffffu, se, off);
        wgt[t] = e / se;
    }
    __syncthreads();

    const float s1 = 1.0f / (1.0f + expf(-lamda1[c]));
    float* orow = out + (size_t)bc * LSEQ;
    for (int i = t; i < LSEQ; i += 256) {
        float g = 0.0f;
        #pragma unroll
        for (int k = 0; k < KSEL; k++) g = fmaf(wgt[k], __bfloat162float(ms[k][i]), g);
        const float s2  = 1.0f / (1.0f + expf(-lamda2[i]));
        const float lam = s1 * s2;
        orow[i] = g * lam + xs[i] * (1.0f - lam);
    }
}

// ---------------------------------------------------------------------------
static void* symaddr(const void* sym)
{
    void* p = nullptr;
    cudaGetSymbolAddress(&p, sym);
    return p;
}

extern "C" void kernel_launch(void* const* d_in, const int* in_sizes, int n_in,
                              void* d_out, int out_size)
{
    const float* x_loc   = (const float*)d_in[0];
    const float* map_raw = (const float*)d_in[1];
    const float* cp_w1   = (const float*)d_in[2];
    const float* cp_b1   = (const float*)d_in[3];
    const float* cp_w2   = (const float*)d_in[4];
    const float* cp_b2   = (const float*)d_in[5];
    const float* de_w1   = (const float*)d_in[6];
    const float* de_b1   = (const float*)d_in[7];
    const float* de_w2   = (const float*)d_in[8];
    const float* de_b2   = (const float*)d_in[9];
    const float* lamda1  = (const float*)d_in[10];
    const float* lamda2  = (const float*)d_in[11];
    const int*   indices = (const int*)d_in[12];
    float* out = (float*)d_out;

    __nv_bfloat16* mapraw = (__nv_bfloat16*)symaddr(g_mapraw);
    __nv_bfloat16* wcp1   = (__nv_bfloat16*)symaddr(g_wcp1);
    __nv_bfloat16* wcp2   = (__nv_bfloat16*)symaddr(g_wcp2);
    __nv_bfloat16* wde1   = (__nv_bfloat16*)symaddr(g_wde1);
    __nv_bfloat16* wde2   = (__nv_bfloat16*)symaddr(g_wde2);
    __nv_bfloat16* h1b    = (__nv_bfloat16*)symaddr(g_h1b);
    __nv_bfloat16* mapTb  = (__nv_bfloat16*)symaddr(g_mapTb);
    __nv_bfloat16* h2b    = (__nv_bfloat16*)symaddr(g_h2b);
    __nv_bfloat16* mapst  = (__nv_bfloat16*)symaddr(g_mapst);

    const int M1 = CHN * LSEQ;   // 32768
    const int M3 = CHN * DCP;    // 16384

    cudaFuncSetAttribute(gemm_bf<INTER, DCP,  true,  false>, cudaFuncAttributeMaxDynamicSharedMemorySize, GSMEM);
    cudaFuncSetAttribute(gemm_bf<DCP,   DCP,  false, true >, cudaFuncAttributeMaxDynamicSharedMemorySize, GSMEM);
    cudaFuncSetAttribute(gemm_bf<LSEQ,  DDE,  true,  false>, cudaFuncAttributeMaxDynamicSharedMemorySize, GSMEM);
    cudaFuncSetAttribute(gemm_bf<DDE,   LSEQ, false, false>, cudaFuncAttributeMaxDynamicSharedMemorySize, GSMEM);

    cvt_all<<<N_CVT_TOT / 4 / 256, 256>>>(map_raw, mapraw, cp_w1, wcp1, cp_w2, wcp2,
                                          de_w1, wde1, de_w2, wde2);

    // GEMM1: (32768,128)@(128,256) + b, relu -> h1 (bf16)
    gemm_bf<INTER, DCP,  true,  false><<<dim3(DCP / BN, M1 / BM), 256, GSMEM>>>(mapraw, wcp1, cp_b1, h1b);
    // GEMM2: (32768,256)@(256,256) + b -> mapT (bf16, transposed store via smem)
    gemm_bf<DCP,   DCP,  false, true ><<<dim3(DCP / BN, M1 / BM), 256, GSMEM>>>(h1b, wcp2, cp_b2, mapTb);
    // GEMM3: (16384,512)@(512,1024) + b, relu -> h2 (bf16)
    gemm_bf<LSEQ,  DDE,  true,  false><<<dim3(DDE / BN, M3 / BM), 256, GSMEM>>>(mapTb, wde1, de_b1, h2b);
    // GEMM4: (16384,1024)@(1024,512) + b -> mapst (bf16)
    gemm_bf<DDE,   LSEQ, false, false><<<dim3(LSEQ / BN, M3 / BM), 256, GSMEM>>>(h2b, wde2, de_b2, mapst);
    // Fused gather/score/softmax/blend (bf16 map_st, cp.async staging)
    fuse_k<<<BATCH * CHN, 256>>>(x_loc, mapst, indices, lamda1, lamda2, out);
}

// round 15
// speedup vs baseline: 1.0988x; 1.0494x over previous
#include <cuda_runtime.h>
#include <cuda_bf16.h>
#include <cstdint>

// Problem constants
#define BATCH 64
#define CHN   64
#define LSEQ  512
#define INTER 128
#define DCP   256
#define DDE   1024
#define KSEL  16
#define SCALE 0.05f

// Scratch (device globals; no runtime allocation)
__device__ __align__(16) __nv_bfloat16 g_mapraw[(size_t)CHN * LSEQ * INTER];
__device__ __align__(16) __nv_bfloat16 g_wcp1[INTER * DCP];
__device__ __align__(16) __nv_bfloat16 g_wcp2[DCP * DCP];
__device__ __align__(16) __nv_bfloat16 g_wde1[LSEQ * DDE];
__device__ __align__(16) __nv_bfloat16 g_wde2[DDE * LSEQ];
__device__ __align__(16) __nv_bfloat16 g_h1b[(size_t)CHN * LSEQ * DCP];
__device__ __align__(16) __nv_bfloat16 g_mapTb[(size_t)CHN * DCP * LSEQ];
__device__ __align__(16) __nv_bfloat16 g_h2b[(size_t)CHN * DCP * DDE];
__device__ __align__(16) __nv_bfloat16 g_mapst[(size_t)CHN * DCP * LSEQ];

__device__ __forceinline__ uint32_t packbf(float lo, float hi) {
    uint32_t r;
    asm("cvt.rn.bf16x2.f32 %0, %1, %2;" : "=r"(r) : "f"(hi), "f"(lo));
    return r;
}

// ---------------------------------------------------------------------------
// Single merged f32->bf16 convert over all 5 tensors.
// ---------------------------------------------------------------------------
#define N_MAPRAW (CHN * LSEQ * INTER)
#define N_WCP1   (INTER * DCP)
#define N_WCP2   (DCP * DCP)
#define N_WDE1   (LSEQ * DDE)
#define N_WDE2   (DDE * LSEQ)
#define N_CVT_TOT (N_MAPRAW + N_WCP1 + N_WCP2 + N_WDE1 + N_WDE2)

__global__ void cvt_all(const float* __restrict__ s0, __nv_bfloat16* __restrict__ d0,
                        const float* __restrict__ s1, __nv_bfloat16* __restrict__ d1,
                        const float* __restrict__ s2, __nv_bfloat16* __restrict__ d2,
                        const float* __restrict__ s3, __nv_bfloat16* __restrict__ d3,
                        const float* __restrict__ s4, __nv_bfloat16* __restrict__ d4)
{
    int i = (blockIdx.x * blockDim.x + threadIdx.x) * 4;
    const float* s;
    __nv_bfloat16* d;
    if (i < N_MAPRAW)                          { s = s0; d = d0; }
    else if ((i -= N_MAPRAW) < N_WCP1)         { s = s1; d = d1; }
    else if ((i -= N_WCP1) < N_WCP2)           { s = s2; d = d2; }
    else if ((i -= N_WCP2) < N_WDE1)           { s = s3; d = d3; }
    else          { i -= N_WDE1;                 s = s4; d = d4; }
    float4 v = *(const float4*)(s + i);
    uint2 o;
    o.x = packbf(v.x, v.y);
    o.y = packbf(v.z, v.w);
    *(uint2*)(d + i) = o;
}

// ---------------------------------------------------------------------------
// BF16 tensor-core GEMM, cp.async 3-stage pipeline + ldmatrix, BK=64.
// 256 threads, 8 warps 4(M)x2(N), warp tile 32x64.
// K, N template parameters; kt loop FULLY UNROLLED (all stage addressing
// folds to immediates; ISSUE guards become compile-time).
// ---------------------------------------------------------------------------
#define BM 128
#define BN 128
#define BK 64
#define STAGES 3
#define ASTAGE 16384
#define BSTAGE 16384
#define GSMEM (STAGES * (ASTAGE + BSTAGE))   // 98304
#define EPI_STRIDE 136

__device__ __forceinline__ void cpasync16(uint32_t saddr, const void* gaddr) {
    asm volatile("cp.async.cg.shared.global [%0], [%1], 16;" :: "r"(saddr), "l"(gaddr));
}
__device__ __forceinline__ void ldsm4(uint32_t& r0, uint32_t& r1, uint32_t& r2, uint32_t& r3, uint32_t a) {
    asm volatile("ldmatrix.sync.aligned.m8n8.x4.shared.b16 {%0,%1,%2,%3}, [%4];"
                 : "=r"(r0), "=r"(r1), "=r"(r2), "=r"(r3) : "r"(a));
}
__device__ __forceinline__ void ldsm4t(uint32_t& r0, uint32_t& r1, uint32_t& r2, uint32_t& r3, uint32_t a) {
    asm volatile("ldmatrix.sync.aligned.m8n8.x4.trans.shared.b16 {%0,%1,%2,%3}, [%4];"
                 : "=r"(r0), "=r"(r1), "=r"(r2), "=r"(r3) : "r"(a));
}

template<int K, int N, bool RELU, bool SWAP>
__global__ __launch_bounds__(256, 2) void gemm_bf(const __nv_bfloat16* __restrict__ A,
                                                  const __nv_bfloat16* __restrict__ B,
                                                  const float* __restrict__ bias,
                                                  __nv_bfloat16* __restrict__ Cout)
{
    extern __shared__ __align__(16) char smem[];
    const uint32_t sA = (uint32_t)__cvta_generic_to_shared(smem);
    const uint32_t sB = sA + STAGES * ASTAGE;

    const int t    = threadIdx.x;
    const int lane = t & 31;
    const int w    = t >> 5;
    const int wm   = (w & 3) * 32;
    const int wn   = (w >> 2) * 64;
    const int bm   = blockIdx.y * BM;
    const int bn   = blockIdx.x * BN;

    constexpr int ntiles = K / BK;

#define ISSUE(kt)                                                                     \
    do {                                                                              \
        if ((kt) < ntiles) {                                                          \
            const uint32_t ab = sA + (uint32_t)(((kt) % STAGES)) * ASTAGE;            \
            const uint32_t bb = sB + (uint32_t)(((kt) % STAGES)) * BSTAGE;            \
            _Pragma("unroll")                                                         \
            for (int q4 = 0; q4 < 4; q4++) {                                          \
                const int qa   = t + q4 * 256;                                        \
                const int arow = qa >> 3;                                             \
                const int acc_ = qa & 7;                                              \
                const uint32_t aoff = (uint32_t)((arow * 8 + (acc_ ^ (arow & 7))) * 16); \
                cpasync16(ab + aoff,                                                  \
                          A + (size_t)(bm + arow) * K + (kt) * BK + acc_ * 8);        \
                const int bk  = qa >> 4;                                              \
                const int bcc = qa & 15;                                              \
                const uint32_t boff = (uint32_t)((bk * 16 + ((bcc & 8) | ((bcc & 7) ^ (bk & 7)))) * 16); \
                cpasync16(bb + boff,                                                  \
                          B + (size_t)((kt) * BK + bk) * N + bn + bcc * 8);           \
            }                                                                         \
        }                                                                             \
        asm volatile("cp.async.commit_group;");                                       \
    } while (0)

    float acc[2][8][4];
    #pragma unroll
    for (int i = 0; i < 2; i++)
        #pragma unroll
        for (int j = 0; j < 8; j++)
            #pragma unroll
            for (int q = 0; q < 4; q++) acc[i][j][q] = 0.0f;

    ISSUE(0);
    ISSUE(1);
    asm volatile("cp.async.wait_group 1;");
    __syncthreads();

    #pragma unroll
    for (int kt = 0; kt < ntiles; kt++) {
        ISSUE(kt + 2);

        const uint32_t curA = sA + (uint32_t)(kt % STAGES) * ASTAGE;
        const uint32_t curB = sB + (uint32_t)(kt % STAGES) * BSTAGE;

        #pragma unroll
        for (int ks = 0; ks < 4; ks++) {
            uint32_t af[2][4];
            {
                const int cch = ks * 2 + (lane >> 4);
                #pragma unroll
                for (int mi = 0; mi < 2; mi++) {
                    const int m = wm + mi * 16 + (lane & 15);
                    const uint32_t a = curA + (uint32_t)((m * 8 + (cch ^ (m & 7))) * 16);
                    ldsm4(af[mi][0], af[mi][1], af[mi][2], af[mi][3], a);
                }
            }
            uint32_t bf[4][4];
            {
                const int k = ks * 16 + (lane & 7) + 8 * ((lane >> 3) & 1);
                const int nc0 = (wn >> 3) + (lane >> 4);
                #pragma unroll
                for (int j = 0; j < 4; j++) {
                    const int nc = nc0 + 2 * j;
                    const uint32_t swz = (uint32_t)((nc & 8) | ((nc & 7) ^ (k & 7)));
                    const uint32_t a = curB + (uint32_t)(k * 256) + swz * 16;
                    ldsm4t(bf[j][0], bf[j][1], bf[j][2], bf[j][3], a);
                }
            }
            #pragma unroll
            for (int ni = 0; ni < 8; ni++) {
                const uint32_t b0 = bf[ni >> 1][(ni & 1) * 2 + 0];
                const uint32_t b1 = bf[ni >> 1][(ni & 1) * 2 + 1];
                #pragma unroll
                for (int mi = 0; mi < 2; mi++) {
                    asm volatile(
                        "mma.sync.aligned.m16n8k16.row.col.f32.bf16.bf16.f32 "
                        "{%0,%1,%2,%3}, {%4,%5,%6,%7}, {%8,%9}, {%0,%1,%2,%3};"
                        : "+f"(acc[mi][ni][0]), "+f"(acc[mi][ni][1]),
                          "+f"(acc[mi][ni][2]), "+f"(acc[mi][ni][3])
                        : "r"(af[mi][0]), "r"(af[mi][1]), "r"(af[mi][2]), "r"(af[mi][3]),
                          "r"(b0), "r"(b1));
                }
            }
        }

        asm volatile("cp.async.wait_group 1;");
        __syncthreads();
    }
#undef ISSUE

    if (SWAP) {
        __nv_bfloat16* epi = (__nv_bfloat16*)smem;
        __syncthreads();
        #pragma unroll
        for (int mi = 0; mi < 2; mi++) {
            const int r = wm + mi * 16 + (lane >> 2);
            #pragma unroll
            for (int ni = 0; ni < 8; ni++) {
                const int col = wn + ni * 8 + 2 * (lane & 3);
                const float bv0 = bias[bn + col];
                const float bv1 = bias[bn + col + 1];
                #pragma unroll
                for (int h = 0; h < 2; h++) {
                    const int m = r + h * 8;
                    float v0 = acc[mi][ni][h * 2 + 0] + bv0;
                    float v1 = acc[mi][ni][h * 2 + 1] + bv1;
                    if (RELU) { v0 = fmaxf(v0, 0.0f); v1 = fmaxf(v1, 0.0f); }
                    epi[(size_t)col * EPI_STRIDE + m]       = __float2bfloat16(v0);
                    epi[(size_t)(col + 1) * EPI_STRIDE + m] = __float2bfloat16(v1);
                }
            }
        }
        __syncthreads();
        const int c  = bm >> 9;
        const int l0 = bm & 511;
        #pragma unroll
        for (int i = t; i < 128 * 16; i += 256) {
            const int col = i >> 4, chunk = i & 15;
            uint4 v = *(uint4*)(epi + (size_t)col * EPI_STRIDE + chunk * 8);
            *(uint4*)(Cout + ((size_t)c * DCP + bn + col) * LSEQ + l0 + chunk * 8) = v;
        }
    } else {
        #pragma unroll
        for (int mi = 0; mi < 2; mi++) {
            const int r = bm + wm + mi * 16 + (lane >> 2);
            #pragma unroll
            for (int ni = 0; ni < 8; ni++) {
                const int col = bn + wn + ni * 8 + 2 * (lane & 3);
                const float bv0 = bias[col];
                const float bv1 = bias[col + 1];
                #pragma unroll
                for (int h = 0; h < 2; h++) {
                    const int m = r + h * 8;
                    float v0 = acc[mi][ni][h * 2 + 0] + bv0;
                    float v1 = acc[mi][ni][h * 2 + 1] + bv1;
                    if (RELU) { v0 = fmaxf(v0, 0.0f); v1 = fmaxf(v1, 0.0f); }
                    *(uint32_t*)(Cout + (size_t)m * N + col) = packbf(v0, v1);
                }
            }
        }
    }
}

// ---------------------------------------------------------------------------
// Fused tail: cp.async gather of K bf16 rows + x, L1 scores, softmax, blend.
// ---------------------------------------------------------------------------
__global__ __launch_bounds__(256) void fuse_k(const float* __restrict__ x_loc,
                                              const __nv_bfloat16* __restrict__ map_st,
                                              const int*   __restrict__ indices,
                                              const float* __restrict__ lamda1,
                                              const float* __restrict__ lamda2,
                                              float* __restrict__ out)
{
    __shared__ __align__(16) float xs[LSEQ];
    __shared__ __align__(16) __nv_bfloat16 ms[KSEL][LSEQ];
    __shared__ float warpsum[KSEL][8];
    __shared__ float wgt[KSEL];

    const int bc = blockIdx.x;
    const int c  = bc & (CHN - 1);
    const int t  = threadIdx.x;

    const uint32_t sxs = (uint32_t)__cvta_generic_to_shared(xs);
    const uint32_t sms = (uint32_t)__cvta_generic_to_shared(ms);

    {
        const float* xrow = x_loc + (size_t)bc * LSEQ;
        if (t < 128) cpasync16(sxs + t * 16, xrow + t * 4);
        #pragma unroll
        for (int q = 0; q < 4; q++) {
            const int idx = t + q * 256;
            const int k = idx >> 6, chunk = idx & 63;
            const int d = indices[bc * KSEL + k];
            cpasync16(sms + (uint32_t)(k * LSEQ * 2 + chunk * 16),
                      map_st + ((size_t)c * DCP + d) * LSEQ + chunk * 8);
        }
        asm volatile("cp.async.commit_group;");
        asm volatile("cp.async.wait_group 0;");
    }
    __syncthreads();

    float part[KSEL];
    #pragma unroll
    for (int k = 0; k < KSEL; k++) part[k] = 0.0f;
    for (int i = t; i < LSEQ; i += 256) {
        const float x = xs[i];
        #pragma unroll
        for (int k = 0; k < KSEL; k++) part[k] += fabsf(x - __bfloat162float(ms[k][i]));
    }

    const int lane = t & 31, w = t >> 5;
    #pragma unroll
    for (int k = 0; k < KSEL; k++) {
        float v = part[k];
        #pragma unroll
        for (int off = 16; off > 0; off >>= 1)
            v += __shfl_down_sync(0xffffffffu, v, off);
        if (lane == 0) warpsum[k][w] = v;
    }
    __syncthreads();

    if (t < KSEL) {
        float s = 0.0f;
        #pragma unroll
        for (int ww = 0; ww < 8; ww++) s += warpsum[t][ww];
        float score = -s * SCALE;
        float mx = score;
        #pragma unroll
        for (int off = 8; off > 0; off >>= 1)
            mx = fmaxf(mx, __shfl_xor_sync(0x0000ffffu, mx, off));
        float e  = expf(score - mx);
        float se = e;
        #pragma unroll
        for (int off = 8; off > 0; off >>= 1)
            se += __shfl_xor_sync(0x0000ffffu, se, off);
        wgt[t] = e / se;
    }
    __syncthreads();

    const float s1 = 1.0f / (1.0f + expf(-lamda1[c]));
    float* orow = out + (size_t)bc * LSEQ;
    for (int i = t; i < LSEQ; i += 256) {
        float g = 0.0f;
        #pragma unroll
        for (int k = 0; k < KSEL; k++) g = fmaf(wgt[k], __bfloat162float(ms[k][i]), g);
        const float s2  = 1.0f / (1.0f + expf(-lamda2[i]));
        const float lam = s1 * s2;
        orow[i] = g * lam + xs[i] * (1.0f - lam);
    }
}

// ---------------------------------------------------------------------------
static void* symaddr(const void* sym)
{
    void* p = nullptr;
    cudaGetSymbolAddress(&p, sym);
    return p;
}

extern "C" void kernel_launch(void* const* d_in, const int* in_sizes, int n_in,
                              void* d_out, int out_size)
{
    const float* x_loc   = (const float*)d_in[0];
    const float* map_raw = (const float*)d_in[1];
    const float* cp_w1   = (const float*)d_in[2];
    const float* cp_b1   = (const float*)d_in[3];
    const float* cp_w2   = (const float*)d_in[4];
    const float* cp_b2   = (const float*)d_in[5];
    const float* de_w1   = (const float*)d_in[6];
    const float* de_b1   = (const float*)d_in[7];
    const float* de_w2   = (const float*)d_in[8];
    const float* de_b2   = (const float*)d_in[9];
    const float* lamda1  = (const float*)d_in[10];
    const float* lamda2  = (const float*)d_in[11];
    const int*   indices = (const int*)d_in[12];
    float* out = (float*)d_out;

    __nv_bfloat16* mapraw = (__nv_bfloat16*)symaddr(g_mapraw);
    __nv_bfloat16* wcp1   = (__nv_bfloat16*)symaddr(g_wcp1);
    __nv_bfloat16* wcp2   = (__nv_bfloat16*)symaddr(g_wcp2);
    __nv_bfloat16* wde1   = (__nv_bfloat16*)symaddr(g_wde1);
    __nv_bfloat16* wde2   = (__nv_bfloat16*)symaddr(g_wde2);
    __nv_bfloat16* h1b    = (__nv_bfloat16*)symaddr(g_h1b);
    __nv_bfloat16* mapTb  = (__nv_bfloat16*)symaddr(g_mapTb);
    __nv_bfloat16* h2b    = (__nv_bfloat16*)symaddr(g_h2b);
    __nv_bfloat16* mapst  = (__nv_bfloat16*)symaddr(g_mapst);

    const int M1 = CHN * LSEQ;   // 32768
    const int M3 = CHN * DCP;    // 16384

    cudaFuncSetAttribute(gemm_bf<INTER, DCP,  true,  false>, cudaFuncAttributeMaxDynamicSharedMemorySize, GSMEM);
    cudaFuncSetAttribute(gemm_bf<DCP,   DCP,  false, true >, cudaFuncAttributeMaxDynamicSharedMemorySize, GSMEM);
    cudaFuncSetAttribute(gemm_bf<LSEQ,  DDE,  true,  false>, cudaFuncAttributeMaxDynamicSharedMemorySize, GSMEM);
    cudaFuncSetAttribute(gemm_bf<DDE,   LSEQ, false, false>, cudaFuncAttributeMaxDynamicSharedMemorySize, GSMEM);

    cvt_all<<<N_CVT_TOT / 4 / 256, 256>>>(map_raw, mapraw, cp_w1, wcp1, cp_w2, wcp2,
                                          de_w1, wde1, de_w2, wde2);

    // GEMM1: (32768,128)@(128,256) + b, relu -> h1 (bf16)
    gemm_bf<INTER, DCP,  true,  false><<<dim3(DCP / BN, M1 / BM), 256, GSMEM>>>(mapraw, wcp1, cp_b1, h1b);
    // GEMM2: (32768,256)@(256,256) + b -> mapT (bf16, transposed store via smem)
    gemm_bf<DCP,   DCP,  false, true ><<<dim3(DCP / BN, M1 / BM), 256, GSMEM>>>(h1b, wcp2, cp_b2, mapTb);
    // GEMM3: (16384,512)@(512,1024) + b, relu -> h2 (bf16)
    gemm_bf<LSEQ,  DDE,  true,  false><<<dim3(DDE / BN, M3 / BM), 256, GSMEM>>>(mapTb, wde1, de_b1, h2b);
    // GEMM4: (16384,1024)@(1024,512) + b -> mapst (bf16)
    gemm_bf<DDE,   LSEQ, false, false><<<dim3(LSEQ / BN, M3 / BM), 256, GSMEM>>>(h2b, wde2, de_b2, mapst);
    // Fused gather/score/softmax/blend (bf16 map_st, cp.async staging)
    fuse_k<<<BATCH * CHN, 256>>>(x_loc, mapst, indices, lamda1, lamda2, out);
}